// round 15
// baseline (speedup 1.0000x reference)
#include <cuda_runtime.h>
#include <cuda_fp16.h>
#include <cstdint>

#define HIDF 128
#define INF 16
#define OUTF 12
#define EPSF 1e-5f
#define NMAX 100000
#define EMAX 1600000
#define NSB  3200

// ---------------- device scratch (static, no allocation) ----------------
__device__ int   g_bad;
__device__ int   g_esrc[EMAX];
__device__ int   g_edst[EMAX];
__device__ int   g_cnt[NMAX];
__device__ int   g_rowptr[NMAX + 1];
__device__ int   g_bsumx[128];
__device__ int   g_src[EMAX];
__device__ float g_nrm[EMAX];
__device__ float g_degf[NMAX];
__device__ float g_dinv[NMAX];
__device__ __align__(16) float  g_aggX[NMAX * INF];
__device__ __align__(16) float  g_bufB[NMAX * HIDF];
__device__ __align__(16) __half g_bufH [NMAX * HIDF];   // layer0 raw fp16; reused for gemm1 out
__device__ __align__(16) __half g_bufHB[NMAX * HIDF];   // agg128 out fp16
__device__ __align__(16) float  g_psum[NSB * HIDF];
__device__ __align__(16) float  g_psq [NSB * HIDF];
__device__ __align__(16) float  g_bn[2 * HIDF];   // [scale, shift]

static inline int cdiv(int a, int b) { return (a + b - 1) / b; }

// ---------------- zero + fused dtype detect (block 0) ----------------
__global__ void k_zero(const void* ei, int E, int n) {
    int i = blockIdx.x * blockDim.x + threadIdx.x;
    if (i < n) { g_cnt[i] = 0; g_degf[i] = 0.0f; }
    if (blockIdx.x == 0) {
        __shared__ int sbad;
        if (threadIdx.x == 0) sbad = 0;
        __syncthreads();
        int t = threadIdx.x;                 // 256 threads sample 1024 values
        int stride = (E > 1024) ? (E / 1024) : 1;
        int bad = 0;
        for (int j = 0; j < 4; j++) {
            long long idx = (long long)(t * 4 + j) * stride;
            if (idx < E) {
                long long v = ((const long long*)ei)[idx];
                if (v < 0 || v >= (long long)n) bad = 1;
            }
        }
        if (bad) sbad = 1;
        __syncthreads();
        if (t == 0) g_bad = sbad;            // sole writer, no init race
    }
}

// ---------------- repack + count + weighted degree (one edge pass) --------
__global__ void k_repack(const void* ei, const float* w, int E) {
    int e = blockIdx.x * blockDim.x + threadIdx.x;
    if (e < E) {
        int s, d;
        if (g_bad) {   // int32 layout
            const int* p = (const int*)ei;
            s = p[e]; d = p[E + e];
        } else {       // genuine int64 layout
            const long long* p = (const long long*)ei;
            s = (int)p[e]; d = (int)p[E + e];
        }
        g_esrc[e] = s;
        g_edst[e] = d;
        atomicAdd(&g_cnt[d], 1);
        atomicAdd(&g_degf[d], w[e]);
    }
}

// ---------------- CSR scan (+ fused dinv; degf complete after repack) -----
__global__ void k_scan_block(int n) {
    __shared__ int sh[256];
    int tid = threadIdx.x;
    int i0 = blockIdx.x * 1024 + tid * 4;
    int v0 = (i0 + 0 < n) ? g_cnt[i0 + 0] : 0;
    int v1 = (i0 + 1 < n) ? g_cnt[i0 + 1] : 0;
    int v2 = (i0 + 2 < n) ? g_cnt[i0 + 2] : 0;
    int v3 = (i0 + 3 < n) ? g_cnt[i0 + 3] : 0;
    int tot = v0 + v1 + v2 + v3;
    sh[tid] = tot;
    __syncthreads();
    for (int d = 1; d < 256; d <<= 1) {
        int t = (tid >= d) ? sh[tid - d] : 0;
        __syncthreads();
        sh[tid] += t;
        __syncthreads();
    }
    int run = sh[tid] - tot;
    run += v0; if (i0 + 0 < n) g_rowptr[i0 + 1] = run;
    run += v1; if (i0 + 1 < n) g_rowptr[i0 + 2] = run;
    run += v2; if (i0 + 2 < n) g_rowptr[i0 + 3] = run;
    run += v3; if (i0 + 3 < n) g_rowptr[i0 + 4] = run;
    if (tid == 255) g_bsumx[blockIdx.x] = sh[255];
#pragma unroll
    for (int j = 0; j < 4; j++) {
        int i = i0 + j;
        if (i < n) g_dinv[i] = rsqrtf(1.0f + g_degf[i]);   // +1 self-loop
    }
}

// ---------------- addoff with fused bsum reduction ----------------
__global__ void k_addoff(int n) {      // grid = nscan, 256 threads
    __shared__ int sh[256];
    int t = threadIdx.x;
    sh[t] = (t < blockIdx.x) ? g_bsumx[t] : 0;   // nscan <= 98 < 128
    __syncthreads();
    for (int d = 128; d > 0; d >>= 1) {
        if (t < d) sh[t] += sh[t + d];
        __syncthreads();
    }
    int base = sh[0];
    int i0 = blockIdx.x * 1024;
    for (int i = i0 + t; i < i0 + 1024; i += 256)
        if (i < n) g_rowptr[i + 1] += base;
    if (blockIdx.x == 0 && t == 0) g_rowptr[0] = 0;
}

// fillcsr: consumes g_cnt via atomicSub; fused normalization
__global__ void k_fillcsr(const float* w, int E) {
    int e = blockIdx.x * blockDim.x + threadIdx.x;
    if (e < E) {
        int src = g_esrc[e];
        int dst = g_edst[e];
        int pos = atomicSub(&g_cnt[dst], 1) - 1;   // 0..count-1 (reverse order)
        int idx = g_rowptr[dst] + pos;
        g_src[idx] = src;
        g_nrm[idx] = g_dinv[src] * w[e] * g_dinv[dst];
    }
}

// ---------------- layer0 aggregation: x (16 feats) -> aggX, float4 --------
__global__ void k_agg16(const float* x, int n) {
    int t = blockIdx.x * blockDim.x + threadIdx.x;   // 4 threads / node
    int node = t >> 2, q = t & 3;
    if (node < n) {
        float di = g_dinv[node];
        float ssc = di * di;
        float4 a = ((const float4*)x)[node * 4 + q];
        a.x *= ssc; a.y *= ssc; a.z *= ssc; a.w *= ssc;
        int s0 = g_rowptr[node], s1 = g_rowptr[node + 1];
        for (int s = s0; s < s1; s++) {
            float nv = g_nrm[s];
            float4 v = ((const float4*)x)[g_src[s] * 4 + q];
            a.x += v.x * nv; a.y += v.y * nv; a.z += v.z * nv; a.w += v.w * nv;
        }
        ((float4*)g_aggX)[node * 4 + q] = a;
    }
}

// ---------------- GEMM0 (+ fused BN stats, raw fp16 out): (N x 16)@(16 x 128)
__global__ void k_gemm0(const float* W, const float* bias, int n) {
    __shared__ float sW[INF * HIDF];
    __shared__ float sx[32 * INF];
    int tid = threadIdx.x;              // 128
    for (int idx = tid; idx < INF * HIDF; idx += 128) sW[idx] = W[idx];
    int base = blockIdx.x * 32;
    for (int idx = tid; idx < 32 * INF; idx += 128) {
        int r = idx >> 4, k = idx & 15;
        sx[idx] = (base + r < n) ? g_aggX[(base + r) * INF + k] : 0.0f;
    }
    __syncthreads();
    int col = tid;
    float wreg[INF];
#pragma unroll
    for (int k = 0; k < INF; k++) wreg[k] = sW[k * HIDF + col];
    float bb = bias[col];
    float ps = 0.0f, pq = 0.0f;
    for (int r = 0; r < 32; r++) {
        if (base + r < n) {
            float acc = bb;
#pragma unroll
            for (int k = 0; k < INF; k++) acc += sx[r * INF + k] * wreg[k];
            g_bufH[(base + r) * HIDF + col] = __float2half(acc);   // raw pre-BN fp16
            ps += acc; pq += acc * acc;                            // exact fp32 stats
        }
    }
    g_psum[blockIdx.x * HIDF + col] = ps;
    g_psq [blockIdx.x * HIDF + col] = pq;
}

// ---------------- BN finalize (parallel over columns) ----------------
__global__ void k_bnfin(const float* g, const float* be, int n, int nsb) {
    __shared__ float ssum[256], ssq[256];
    int c = blockIdx.x;                 // 0..127
    int t = threadIdx.x;                // 256
    float s = 0.0f, s2 = 0.0f;
    for (int b = t; b < nsb; b += 256) {
        s  += g_psum[b * HIDF + c];
        s2 += g_psq [b * HIDF + c];
    }
    ssum[t] = s; ssq[t] = s2;
    __syncthreads();
    for (int d = 128; d > 0; d >>= 1) {
        if (t < d) { ssum[t] += ssum[t + d]; ssq[t] += ssq[t + d]; }
        __syncthreads();
    }
    if (t == 0) {
        float inv_n = 1.0f / (float)n;
        float mean = ssum[0] * inv_n;
        float var = ssq[0] * inv_n - mean * mean;
        float sc = g[c] * rsqrtf(var + EPSF);
        g_bn[c] = sc;
        g_bn[HIDF + c] = be[c] - mean * sc;
    }
}

// ---------------- layer1 aggregation over raw fp16, BN+ReLU inline, fp16 out
__global__ void k_agg128(int n) {
    int t = blockIdx.x * blockDim.x + threadIdx.x;
    int node = t >> 5, lane = t & 31;
    if (node < n) {
        float4 sc4 = ((const float4*)g_bn)[lane];
        float4 sh4 = ((const float4*)g_bn)[32 + lane];
        float di = g_dinv[node];
        float ssc = di * di;
        float4 a;
        {
            uint2 raw = ((const uint2*)g_bufH)[node * 32 + lane];
            float2 f0 = __half22float2(*(__half2*)&raw.x);
            float2 f1 = __half22float2(*(__half2*)&raw.y);
            a.x = fmaxf(f0.x * sc4.x + sh4.x, 0.0f) * ssc;
            a.y = fmaxf(f0.y * sc4.y + sh4.y, 0.0f) * ssc;
            a.z = fmaxf(f1.x * sc4.z + sh4.z, 0.0f) * ssc;
            a.w = fmaxf(f1.y * sc4.w + sh4.w, 0.0f) * ssc;
        }
        int s0 = g_rowptr[node], s1 = g_rowptr[node + 1];
        for (int s = s0; s < s1; s++) {
            int src = g_src[s];               // broadcast within warp
            float nv = g_nrm[s];
            uint2 raw = ((const uint2*)g_bufH)[src * 32 + lane];
            float2 f0 = __half22float2(*(__half2*)&raw.x);
            float2 f1 = __half22float2(*(__half2*)&raw.y);
            a.x += fmaxf(f0.x * sc4.x + sh4.x, 0.0f) * nv;
            a.y += fmaxf(f0.y * sc4.y + sh4.y, 0.0f) * nv;
            a.z += fmaxf(f1.x * sc4.z + sh4.z, 0.0f) * nv;
            a.w += fmaxf(f1.y * sc4.w + sh4.w, 0.0f) * nv;
        }
        __half2 h0 = __floats2half2_rn(a.x, a.y);
        __half2 h1 = __floats2half2_rn(a.z, a.w);
        uint2 o;
        o.x = *(unsigned*)&h0;
        o.y = *(unsigned*)&h1;
        ((uint2*)g_bufHB)[node * 32 + lane] = o;
    }
}

// ---------------- GEMM1 (FFMA, 128x128 tile, fp16 in/out, + fused BN stats)
__global__ void k_gemm1(const float* W, const float* bias, int n) {
    __shared__ float As[16][136];       // [k][row], stride 136 -> conflict-free
    __shared__ float Bs[16][128];       // [k][col]
    __shared__ float sSum[16][128];
    __shared__ float sSq [16][128];
    int tid = threadIdx.x;              // 256
    int tr = tid >> 4;                  // 0..15
    int tc = tid & 15;                  // 0..15
    int r0 = tr * 8;
    int c0 = tc * 4;                    // cols c0..c0+3 and c0+64..c0+67
    int rowBase = blockIdx.x * 128;

    float acc[8][8];
#pragma unroll
    for (int i = 0; i < 8; i++)
#pragma unroll
        for (int j = 0; j < 8; j++) acc[i][j] = 0.0f;

    for (int kk = 0; kk < HIDF; kk += 16) {
        // A tile: 128 rows x 16 k from fp16 bufHB
#pragma unroll
        for (int l = tid; l < 512; l += 256) {
            int r = l >> 2, q = l & 3;
            int row = rowBase + r;
            float2 f0 = make_float2(0.f, 0.f), f1 = make_float2(0.f, 0.f);
            if (row < n) {
                uint2 raw = ((const uint2*)g_bufHB)[row * 32 + (kk >> 2) + q];
                f0 = __half22float2(*(__half2*)&raw.x);
                f1 = __half22float2(*(__half2*)&raw.y);
            }
            As[q * 4 + 0][r] = f0.x; As[q * 4 + 1][r] = f0.y;
            As[q * 4 + 2][r] = f1.x; As[q * 4 + 3][r] = f1.y;
        }
#pragma unroll
        for (int l = tid; l < 512; l += 256) {
            int k = l >> 5, q = l & 31;
            *(float4*)&Bs[k][q * 4] = *(const float4*)&W[(kk + k) * HIDF + q * 4];
        }
        __syncthreads();
#pragma unroll
        for (int k = 0; k < 16; k++) {
            float4 a0 = *(const float4*)&As[k][r0];
            float4 a1 = *(const float4*)&As[k][r0 + 4];
            float4 b0 = *(const float4*)&Bs[k][c0];
            float4 b1 = *(const float4*)&Bs[k][c0 + 64];
            float ar[8] = {a0.x, a0.y, a0.z, a0.w, a1.x, a1.y, a1.z, a1.w};
            float br[8] = {b0.x, b0.y, b0.z, b0.w, b1.x, b1.y, b1.z, b1.w};
#pragma unroll
            for (int i = 0; i < 8; i++)
#pragma unroll
                for (int j = 0; j < 8; j++)
                    acc[i][j] += ar[i] * br[j];
        }
        __syncthreads();
    }
    float bb[8];
#pragma unroll
    for (int j = 0; j < 4; j++) { bb[j] = bias[c0 + j]; bb[4 + j] = bias[c0 + 64 + j]; }
    float ls[8] = {0,0,0,0,0,0,0,0};
    float lq[8] = {0,0,0,0,0,0,0,0};
#pragma unroll
    for (int i = 0; i < 8; i++) {
        int row = rowBase + r0 + i;
        if (row < n) {
            float v0 = acc[i][0] + bb[0], v1 = acc[i][1] + bb[1];
            float v2 = acc[i][2] + bb[2], v3 = acc[i][3] + bb[3];
            float v4 = acc[i][4] + bb[4], v5 = acc[i][5] + bb[5];
            float v6 = acc[i][6] + bb[6], v7 = acc[i][7] + bb[7];
            ls[0] += v0; lq[0] += v0 * v0;  ls[1] += v1; lq[1] += v1 * v1;
            ls[2] += v2; lq[2] += v2 * v2;  ls[3] += v3; lq[3] += v3 * v3;
            ls[4] += v4; lq[4] += v4 * v4;  ls[5] += v5; lq[5] += v5 * v5;
            ls[6] += v6; lq[6] += v6 * v6;  ls[7] += v7; lq[7] += v7 * v7;
            __half2 h0 = __floats2half2_rn(v0, v1);
            __half2 h1 = __floats2half2_rn(v2, v3);
            __half2 h2 = __floats2half2_rn(v4, v5);
            __half2 h3 = __floats2half2_rn(v6, v7);
            uint2 oa, ob;
            oa.x = *(unsigned*)&h0; oa.y = *(unsigned*)&h1;
            ob.x = *(unsigned*)&h2; ob.y = *(unsigned*)&h3;
            // raw pre-BN fp16 into g_bufH (dead after agg128; reuse)
            *(uint2*)&g_bufH[row * HIDF + c0]      = oa;
            *(uint2*)&g_bufH[row * HIDF + c0 + 64] = ob;
        }
    }
#pragma unroll
    for (int j = 0; j < 4; j++) {
        sSum[tr][c0 + j] = ls[j];      sSum[tr][c0 + 64 + j] = ls[4 + j];
        sSq [tr][c0 + j] = lq[j];      sSq [tr][c0 + 64 + j] = lq[4 + j];
    }
    __syncthreads();
    if (tid < 128) {
        float s = 0.0f, q = 0.0f;
#pragma unroll
        for (int t = 0; t < 16; t++) { s += sSum[t][tid]; q += sSq[t][tid]; }
        g_psum[blockIdx.x * HIDF + tid] = s;
        g_psq [blockIdx.x * HIDF + tid] = q;
    }
}

// ---------------- GEMM2 (fp16 in, BN+ReLU fused on load): (N x 128)@(128 x 12)
__global__ void k_gemm2(const float* W, int n) {
    __shared__ float sW[HIDF * OUTF];    // 6KB
    __shared__ float sin[32 * HIDF];     // 16KB
    int tid = threadIdx.x;               // 384
    for (int idx = tid; idx < HIDF * OUTF; idx += 384) sW[idx] = W[idx];
    int base = blockIdx.x * 32;
    for (int idx = tid; idx < 32 * HIDF / 4; idx += 384) {   // 1024 quads
        int r = idx >> 5, q = idx & 31;
        float4 v = make_float4(0.f, 0.f, 0.f, 0.f);
        if (base + r < n) {
            uint2 raw = ((const uint2*)g_bufH)[(base + r) * 32 + q];
            float2 f0 = __half22float2(*(__half2*)&raw.x);
            float2 f1 = __half22float2(*(__half2*)&raw.y);
            float4 sc = ((const float4*)g_bn)[q];
            float4 sh = ((const float4*)g_bn)[32 + q];
            v.x = fmaxf(f0.x * sc.x + sh.x, 0.0f);
            v.y = fmaxf(f0.y * sc.y + sh.y, 0.0f);
            v.z = fmaxf(f1.x * sc.z + sh.z, 0.0f);
            v.w = fmaxf(f1.y * sc.w + sh.w, 0.0f);
        }
        *(float4*)&sin[r * HIDF + q * 4] = v;
    }
    __syncthreads();
    int c = tid % 12, r = tid / 12;      // r 0..31
    if (r < 32 && base + r < n) {
        float acc = 0.0f;
#pragma unroll 8
        for (int k = 0; k < HIDF; k++) acc += sin[r * HIDF + k] * sW[k * OUTF + c];
        g_bufB[(base + r) * OUTF + c] = acc;
    }
}

// ---------------- final aggregation (12 feats): bufB -> out, fused bias ----
__global__ void k_agg12(float* out, const float* b2, int n) {
    int t = blockIdx.x * blockDim.x + threadIdx.x;
    int node = t >> 4, f = t & 15;
    if (node < n && f < OUTF) {
        float di = g_dinv[node];
        float a = g_bufB[node * OUTF + f] * di * di + b2[f];
        int s0 = g_rowptr[node], s1 = g_rowptr[node + 1];
        for (int s = s0; s < s1; s++)
            a += g_bufB[g_src[s] * OUTF + f] * g_nrm[s];
        out[node * OUTF + f] = a;
    }
}

// ---------------- launch ----------------
extern "C" void kernel_launch(void* const* d_in, const int* in_sizes, int n_in,
                              void* d_out, int out_size) {
    const float* x   = (const float*)d_in[0];
    const void*  ei  = d_in[1];
    const float* w   = (const float*)d_in[2];
    const float* W0  = (const float*)d_in[3];
    const float* b0  = (const float*)d_in[4];
    const float* W1  = (const float*)d_in[5];
    const float* b1  = (const float*)d_in[6];
    const float* W2  = (const float*)d_in[7];
    const float* b2  = (const float*)d_in[8];
    const float* g0  = (const float*)d_in[9];
    const float* be0 = (const float*)d_in[10];
    const float* g1  = (const float*)d_in[11];
    const float* be1 = (const float*)d_in[12];
    float* out = (float*)d_out;

    int n = in_sizes[0] / INF;
    int E = in_sizes[2];
    const int B = 256;
    int nscan = cdiv(n, 1024);
    int nsb0 = cdiv(n, 32);     // gemm0 stat blocks
    int nsb1 = cdiv(n, 128);    // gemm1 stat blocks

    // zero (+detect) + repack(+count+deg)
    k_zero<<<cdiv(n, B), B>>>(ei, E, n);
    k_repack<<<cdiv(E, B), B>>>(ei, w, E);

    // CSR build
    k_scan_block<<<nscan, 256>>>(n);
    k_addoff<<<nscan, 256>>>(n);
    k_fillcsr<<<cdiv(E, B), B>>>(w, E);

    // layer 0 (stats fused in gemm0; raw fp16 output)
    k_agg16<<<cdiv(n * 4, B), B>>>(x, n);
    k_gemm0<<<nsb0, 128>>>(W0, b0, n);
    k_bnfin<<<HIDF, 256>>>(g0, be0, n, nsb0);

    // layer 1 (BN+ReLU inline in fp16 gather; fp16 out; fp16-in GEMM; stats fused)
    k_agg128<<<cdiv(n * 32, B), B>>>(n);
    k_gemm1<<<cdiv(n, 128), 256>>>(W1, b1, n);
    k_bnfin<<<HIDF, 256>>>(g1, be1, n, nsb1);

    // layer 2 (fp16-in gemm2 with BN fused; transform then aggregate)
    k_gemm2<<<cdiv(n, 32), 384>>>(W2, n);
    k_agg12<<<cdiv(n * 16, B), B>>>(out, b2, n);
}

// round 16
// speedup vs baseline: 1.0394x; 1.0394x over previous
#include <cuda_runtime.h>
#include <cuda_fp16.h>
#include <cstdint>

#define HIDF 128
#define INF 16
#define OUTF 12
#define EPSF 1e-5f
#define NMAX 100000
#define EMAX 1600000
#define NSB  3200

// ---------------- device scratch (static, no allocation) ----------------
__device__ int   g_bad;
__device__ int   g_esrc[EMAX];
__device__ int   g_edst[EMAX];
__device__ int   g_cnt[NMAX];
__device__ int   g_rowptr[NMAX + 1];
__device__ int   g_bsumx[128];
__device__ int   g_src[EMAX];
__device__ float g_nrm[EMAX];
__device__ float g_degf[NMAX];
__device__ float g_dinv[NMAX];
__device__ __align__(16) float  g_aggX[NMAX * INF];
__device__ __align__(16) float  g_bufA[NMAX * HIDF];
__device__ __align__(16) float  g_bufB[NMAX * HIDF];
__device__ __align__(16) __half g_bufH[NMAX * HIDF];
__device__ __align__(16) float  g_psum[NSB * HIDF];
__device__ __align__(16) float  g_psq [NSB * HIDF];
__device__ __align__(16) float  g_bn[2 * HIDF];   // [scale, shift]

static inline int cdiv(int a, int b) { return (a + b - 1) / b; }

// ---------------- zero + fused dtype detect (block 0) ----------------
__global__ void k_zero(const void* ei, int E, int n) {
    int i = blockIdx.x * blockDim.x + threadIdx.x;
    if (i < n) { g_cnt[i] = 0; g_degf[i] = 0.0f; }
    if (blockIdx.x == 0) {
        __shared__ int sbad;
        if (threadIdx.x == 0) sbad = 0;
        __syncthreads();
        int t = threadIdx.x;                 // 256 threads sample 1024 values
        int stride = (E > 1024) ? (E / 1024) : 1;
        int bad = 0;
        for (int j = 0; j < 4; j++) {
            long long idx = (long long)(t * 4 + j) * stride;
            if (idx < E) {
                long long v = ((const long long*)ei)[idx];
                if (v < 0 || v >= (long long)n) bad = 1;
            }
        }
        if (bad) sbad = 1;
        __syncthreads();
        if (t == 0) g_bad = sbad;            // sole writer, no init race
    }
}

// ---------------- repack + count + weighted degree (one edge pass) --------
__global__ void k_repack(const void* ei, const float* w, int E) {
    int e = blockIdx.x * blockDim.x + threadIdx.x;
    if (e < E) {
        int s, d;
        if (g_bad) {   // int32 layout
            const int* p = (const int*)ei;
            s = p[e]; d = p[E + e];
        } else {       // genuine int64 layout
            const long long* p = (const long long*)ei;
            s = (int)p[e]; d = (int)p[E + e];
        }
        g_esrc[e] = s;
        g_edst[e] = d;
        atomicAdd(&g_cnt[d], 1);
        atomicAdd(&g_degf[d], w[e]);
    }
}

// ---------------- CSR scan (+ fused dinv; degf complete after repack) -----
__global__ void k_scan_block(int n) {
    __shared__ int sh[256];
    int tid = threadIdx.x;
    int i0 = blockIdx.x * 1024 + tid * 4;
    int v0 = (i0 + 0 < n) ? g_cnt[i0 + 0] : 0;
    int v1 = (i0 + 1 < n) ? g_cnt[i0 + 1] : 0;
    int v2 = (i0 + 2 < n) ? g_cnt[i0 + 2] : 0;
    int v3 = (i0 + 3 < n) ? g_cnt[i0 + 3] : 0;
    int tot = v0 + v1 + v2 + v3;
    sh[tid] = tot;
    __syncthreads();
    for (int d = 1; d < 256; d <<= 1) {
        int t = (tid >= d) ? sh[tid - d] : 0;
        __syncthreads();
        sh[tid] += t;
        __syncthreads();
    }
    int run = sh[tid] - tot;
    run += v0; if (i0 + 0 < n) g_rowptr[i0 + 1] = run;
    run += v1; if (i0 + 1 < n) g_rowptr[i0 + 2] = run;
    run += v2; if (i0 + 2 < n) g_rowptr[i0 + 3] = run;
    run += v3; if (i0 + 3 < n) g_rowptr[i0 + 4] = run;
    if (tid == 255) g_bsumx[blockIdx.x] = sh[255];
#pragma unroll
    for (int j = 0; j < 4; j++) {
        int i = i0 + j;
        if (i < n) g_dinv[i] = rsqrtf(1.0f + g_degf[i]);   // +1 self-loop
    }
}

// ---------------- addoff with fused bsum reduction ----------------
__global__ void k_addoff(int n) {      // grid = nscan, 256 threads
    __shared__ int sh[256];
    int t = threadIdx.x;
    sh[t] = (t < blockIdx.x) ? g_bsumx[t] : 0;   // nscan <= 98 < 128
    __syncthreads();
    for (int d = 128; d > 0; d >>= 1) {
        if (t < d) sh[t] += sh[t + d];
        __syncthreads();
    }
    int base = sh[0];
    int i0 = blockIdx.x * 1024;
    for (int i = i0 + t; i < i0 + 1024; i += 256)
        if (i < n) g_rowptr[i + 1] += base;
    if (blockIdx.x == 0 && t == 0) g_rowptr[0] = 0;
}

// fillcsr: consumes g_cnt via atomicSub; fused normalization
__global__ void k_fillcsr(const float* w, int E) {
    int e = blockIdx.x * blockDim.x + threadIdx.x;
    if (e < E) {
        int src = g_esrc[e];
        int dst = g_edst[e];
        int pos = atomicSub(&g_cnt[dst], 1) - 1;   // 0..count-1 (reverse order)
        int idx = g_rowptr[dst] + pos;
        g_src[idx] = src;
        g_nrm[idx] = g_dinv[src] * w[e] * g_dinv[dst];
    }
}

// ---------------- layer0 aggregation: x (16 feats) -> aggX, float4 --------
__global__ void k_agg16(const float* x, int n) {
    int t = blockIdx.x * blockDim.x + threadIdx.x;   // 4 threads / node
    int node = t >> 2, q = t & 3;
    if (node < n) {
        float di = g_dinv[node];
        float ssc = di * di;
        float4 a = ((const float4*)x)[node * 4 + q];
        a.x *= ssc; a.y *= ssc; a.z *= ssc; a.w *= ssc;
        int s0 = g_rowptr[node], s1 = g_rowptr[node + 1];
        for (int s = s0; s < s1; s++) {
            float nv = g_nrm[s];
            float4 v = ((const float4*)x)[g_src[s] * 4 + q];
            a.x += v.x * nv; a.y += v.y * nv; a.z += v.z * nv; a.w += v.w * nv;
        }
        ((float4*)g_aggX)[node * 4 + q] = a;
    }
}

// ---------------- GEMM0 (+ fused BN stats, raw fp16 out): (N x 16)@(16 x 128)
__global__ void k_gemm0(const float* W, const float* bias, int n) {
    __shared__ float sW[INF * HIDF];
    __shared__ float sx[32 * INF];
    int tid = threadIdx.x;              // 128
    for (int idx = tid; idx < INF * HIDF; idx += 128) sW[idx] = W[idx];
    int base = blockIdx.x * 32;
    for (int idx = tid; idx < 32 * INF; idx += 128) {
        int r = idx >> 4, k = idx & 15;
        sx[idx] = (base + r < n) ? g_aggX[(base + r) * INF + k] : 0.0f;
    }
    __syncthreads();
    int col = tid;
    float wreg[INF];
#pragma unroll
    for (int k = 0; k < INF; k++) wreg[k] = sW[k * HIDF + col];
    float bb = bias[col];
    float ps = 0.0f, pq = 0.0f;
    for (int r = 0; r < 32; r++) {
        if (base + r < n) {
            float acc = bb;
#pragma unroll
            for (int k = 0; k < INF; k++) acc += sx[r * INF + k] * wreg[k];
            g_bufH[(base + r) * HIDF + col] = __float2half(acc);   // raw pre-BN fp16
            ps += acc; pq += acc * acc;                            // exact fp32 stats
        }
    }
    g_psum[blockIdx.x * HIDF + col] = ps;
    g_psq [blockIdx.x * HIDF + col] = pq;
}

// ---------------- BN finalize (parallel over columns) ----------------
__global__ void k_bnfin(const float* g, const float* be, int n, int nsb) {
    __shared__ float ssum[256], ssq[256];
    int c = blockIdx.x;                 // 0..127
    int t = threadIdx.x;                // 256
    float s = 0.0f, s2 = 0.0f;
    for (int b = t; b < nsb; b += 256) {
        s  += g_psum[b * HIDF + c];
        s2 += g_psq [b * HIDF + c];
    }
    ssum[t] = s; ssq[t] = s2;
    __syncthreads();
    for (int d = 128; d > 0; d >>= 1) {
        if (t < d) { ssum[t] += ssum[t + d]; ssq[t] += ssq[t + d]; }
        __syncthreads();
    }
    if (t == 0) {
        float inv_n = 1.0f / (float)n;
        float mean = ssum[0] * inv_n;
        float var = ssq[0] * inv_n - mean * mean;
        float sc = g[c] * rsqrtf(var + EPSF);
        g_bn[c] = sc;
        g_bn[HIDF + c] = be[c] - mean * sc;
    }
}

// ---------------- layer1 aggregation over raw fp16, BN+ReLU inline --------
__global__ void k_agg128(int n) {
    int t = blockIdx.x * blockDim.x + threadIdx.x;
    int node = t >> 5, lane = t & 31;
    if (node < n) {
        float4 sc4 = ((const float4*)g_bn)[lane];
        float4 sh4 = ((const float4*)g_bn)[32 + lane];
        float di = g_dinv[node];
        float ssc = di * di;
        float4 a;
        {
            uint2 raw = ((const uint2*)g_bufH)[node * 32 + lane];
            float2 f0 = __half22float2(*(__half2*)&raw.x);
            float2 f1 = __half22float2(*(__half2*)&raw.y);
            a.x = fmaxf(f0.x * sc4.x + sh4.x, 0.0f) * ssc;
            a.y = fmaxf(f0.y * sc4.y + sh4.y, 0.0f) * ssc;
            a.z = fmaxf(f1.x * sc4.z + sh4.z, 0.0f) * ssc;
            a.w = fmaxf(f1.y * sc4.w + sh4.w, 0.0f) * ssc;
        }
        int s0 = g_rowptr[node], s1 = g_rowptr[node + 1];
        for (int s = s0; s < s1; s++) {
            int src = g_src[s];               // broadcast within warp
            float nv = g_nrm[s];
            uint2 raw = ((const uint2*)g_bufH)[src * 32 + lane];
            float2 f0 = __half22float2(*(__half2*)&raw.x);
            float2 f1 = __half22float2(*(__half2*)&raw.y);
            a.x += fmaxf(f0.x * sc4.x + sh4.x, 0.0f) * nv;
            a.y += fmaxf(f0.y * sc4.y + sh4.y, 0.0f) * nv;
            a.z += fmaxf(f1.x * sc4.z + sh4.z, 0.0f) * nv;
            a.w += fmaxf(f1.y * sc4.w + sh4.w, 0.0f) * nv;
        }
        ((float4*)g_bufB)[node * 32 + lane] = a;
    }
}

// ---------------- GEMM1 (FFMA, 128x128 tile, 8x8/thread, + fused BN stats)
__global__ void k_gemm1(const float* W, const float* bias, int n) {
    __shared__ float As[16][136];       // [k][row], stride 136 -> conflict-free
    __shared__ float Bs[16][128];       // [k][col]
    __shared__ float sSum[16][128];
    __shared__ float sSq [16][128];
    int tid = threadIdx.x;              // 256
    int tr = tid >> 4;                  // 0..15
    int tc = tid & 15;                  // 0..15
    int r0 = tr * 8;
    int c0 = tc * 4;                    // cols c0..c0+3 and c0+64..c0+67
    int rowBase = blockIdx.x * 128;

    float acc[8][8];
#pragma unroll
    for (int i = 0; i < 8; i++)
#pragma unroll
        for (int j = 0; j < 8; j++) acc[i][j] = 0.0f;

    for (int kk = 0; kk < HIDF; kk += 16) {
#pragma unroll
        for (int l = tid; l < 512; l += 256) {
            int r = l >> 2, q = l & 3;
            int row = rowBase + r;
            float4 a = make_float4(0.f, 0.f, 0.f, 0.f);
            if (row < n) a = *(const float4*)&g_bufB[row * HIDF + kk + q * 4];
            As[q * 4 + 0][r] = a.x; As[q * 4 + 1][r] = a.y;
            As[q * 4 + 2][r] = a.z; As[q * 4 + 3][r] = a.w;
        }
#pragma unroll
        for (int l = tid; l < 512; l += 256) {
            int k = l >> 5, q = l & 31;
            *(float4*)&Bs[k][q * 4] = *(const float4*)&W[(kk + k) * HIDF + q * 4];
        }
        __syncthreads();
#pragma unroll
        for (int k = 0; k < 16; k++) {
            float4 a0 = *(const float4*)&As[k][r0];
            float4 a1 = *(const float4*)&As[k][r0 + 4];
            float4 b0 = *(const float4*)&Bs[k][c0];
            float4 b1 = *(const float4*)&Bs[k][c0 + 64];
            float ar[8] = {a0.x, a0.y, a0.z, a0.w, a1.x, a1.y, a1.z, a1.w};
            float br[8] = {b0.x, b0.y, b0.z, b0.w, b1.x, b1.y, b1.z, b1.w};
#pragma unroll
            for (int i = 0; i < 8; i++)
#pragma unroll
                for (int j = 0; j < 8; j++)
                    acc[i][j] += ar[i] * br[j];
        }
        __syncthreads();
    }
    float bb[8];
#pragma unroll
    for (int j = 0; j < 4; j++) { bb[j] = bias[c0 + j]; bb[4 + j] = bias[c0 + 64 + j]; }
    float ls[8] = {0,0,0,0,0,0,0,0};
    float lq[8] = {0,0,0,0,0,0,0,0};
#pragma unroll
    for (int i = 0; i < 8; i++) {
        int row = rowBase + r0 + i;
        if (row < n) {
            float4 o0, o1;
            float v;
            v = acc[i][0] + bb[0]; o0.x = v; ls[0] += v; lq[0] += v * v;
            v = acc[i][1] + bb[1]; o0.y = v; ls[1] += v; lq[1] += v * v;
            v = acc[i][2] + bb[2]; o0.z = v; ls[2] += v; lq[2] += v * v;
            v = acc[i][3] + bb[3]; o0.w = v; ls[3] += v; lq[3] += v * v;
            v = acc[i][4] + bb[4]; o1.x = v; ls[4] += v; lq[4] += v * v;
            v = acc[i][5] + bb[5]; o1.y = v; ls[5] += v; lq[5] += v * v;
            v = acc[i][6] + bb[6]; o1.z = v; ls[6] += v; lq[6] += v * v;
            v = acc[i][7] + bb[7]; o1.w = v; ls[7] += v; lq[7] += v * v;
            *(float4*)&g_bufA[row * HIDF + c0]      = o0;
            *(float4*)&g_bufA[row * HIDF + c0 + 64] = o1;
        }
    }
#pragma unroll
    for (int j = 0; j < 4; j++) {
        sSum[tr][c0 + j] = ls[j];      sSum[tr][c0 + 64 + j] = ls[4 + j];
        sSq [tr][c0 + j] = lq[j];      sSq [tr][c0 + 64 + j] = lq[4 + j];
    }
    __syncthreads();
    if (tid < 128) {
        float s = 0.0f, q = 0.0f;
#pragma unroll
        for (int t = 0; t < 16; t++) { s += sSum[t][tid]; q += sSq[t][tid]; }
        g_psum[blockIdx.x * HIDF + tid] = s;
        g_psq [blockIdx.x * HIDF + tid] = q;
    }
}

// ---------------- GEMM2 (BN+ReLU fused on load): (N x 128) @ (128 x 12) -> bufB
__global__ void k_gemm2(const float* W, int n) {
    __shared__ float sW[HIDF * OUTF];    // 6KB
    __shared__ float sin[32 * HIDF];     // 16KB
    int tid = threadIdx.x;               // 384
    for (int idx = tid; idx < HIDF * OUTF; idx += 384) sW[idx] = W[idx];
    int base = blockIdx.x * 32;
    for (int idx = tid; idx < 32 * HIDF / 4; idx += 384) {   // 1024 float4
        int r = idx >> 5, q = idx & 31;
        float4 v = make_float4(0.f, 0.f, 0.f, 0.f);
        if (base + r < n) {
            float4 raw = *(const float4*)&g_bufA[(base + r) * HIDF + q * 4];
            float4 sc = ((const float4*)g_bn)[q];
            float4 sh = ((const float4*)g_bn)[32 + q];
            v.x = fmaxf(raw.x * sc.x + sh.x, 0.0f);
            v.y = fmaxf(raw.y * sc.y + sh.y, 0.0f);
            v.z = fmaxf(raw.z * sc.z + sh.z, 0.0f);
            v.w = fmaxf(raw.w * sc.w + sh.w, 0.0f);
        }
        *(float4*)&sin[r * HIDF + q * 4] = v;
    }
    __syncthreads();
    int c = tid % 12, r = tid / 12;      // r 0..31
    if (r < 32 && base + r < n) {
        float acc = 0.0f;
#pragma unroll 8
        for (int k = 0; k < HIDF; k++) acc += sin[r * HIDF + k] * sW[k * OUTF + c];
        g_bufB[(base + r) * OUTF + c] = acc;
    }
}

// ---------------- final aggregation (12 feats, float4): bufB -> out -------
__global__ void k_agg12(float* out, const float* b2, int n) {
    int t = blockIdx.x * blockDim.x + threadIdx.x;   // 3 float4-threads / node
    int node = t / 3, q = t - node * 3;
    if (node < n) {
        float di = g_dinv[node];
        float ssc = di * di;
        float4 a  = ((const float4*)g_bufB)[node * 3 + q];
        float4 bb = ((const float4*)b2)[q];
        a.x = a.x * ssc + bb.x; a.y = a.y * ssc + bb.y;
        a.z = a.z * ssc + bb.z; a.w = a.w * ssc + bb.w;
        int s0 = g_rowptr[node], s1 = g_rowptr[node + 1];
        for (int s = s0; s < s1; s++) {
            float nv = g_nrm[s];
            float4 v = ((const float4*)g_bufB)[g_src[s] * 3 + q];
            a.x += v.x * nv; a.y += v.y * nv; a.z += v.z * nv; a.w += v.w * nv;
        }
        ((float4*)out)[node * 3 + q] = a;
    }
}

// ---------------- launch ----------------
extern "C" void kernel_launch(void* const* d_in, const int* in_sizes, int n_in,
                              void* d_out, int out_size) {
    const float* x   = (const float*)d_in[0];
    const void*  ei  = d_in[1];
    const float* w   = (const float*)d_in[2];
    const float* W0  = (const float*)d_in[3];
    const float* b0  = (const float*)d_in[4];
    const float* W1  = (const float*)d_in[5];
    const float* b1  = (const float*)d_in[6];
    const float* W2  = (const float*)d_in[7];
    const float* b2  = (const float*)d_in[8];
    const float* g0  = (const float*)d_in[9];
    const float* be0 = (const float*)d_in[10];
    const float* g1  = (const float*)d_in[11];
    const float* be1 = (const float*)d_in[12];
    float* out = (float*)d_out;

    int n = in_sizes[0] / INF;
    int E = in_sizes[2];
    const int B = 256;
    int nscan = cdiv(n, 1024);
    int nsb0 = cdiv(n, 32);     // gemm0 stat blocks
    int nsb1 = cdiv(n, 128);    // gemm1 stat blocks

    // zero (+detect) + repack(+count+deg)
    k_zero<<<cdiv(n, B), B>>>(ei, E, n);
    k_repack<<<cdiv(E, B), B>>>(ei, w, E);

    // CSR build
    k_scan_block<<<nscan, 256>>>(n);
    k_addoff<<<nscan, 256>>>(n);
    k_fillcsr<<<cdiv(E, B), B>>>(w, E);

    // layer 0 (stats fused in gemm0 epilogue; raw fp16 output)
    k_agg16<<<cdiv(n * 4, B), B>>>(x, n);
    k_gemm0<<<nsb0, 128>>>(W0, b0, n);
    k_bnfin<<<HIDF, 256>>>(g0, be0, n, nsb0);

    // layer 1 (BN+ReLU applied inline during fp16 gather; stats fused in gemm1)
    k_agg128<<<cdiv(n * 32, B), B>>>(n);
    k_gemm1<<<cdiv(n, 128), 256>>>(W1, b1, n);
    k_bnfin<<<HIDF, 256>>>(g1, be1, n, nsb1);

    // layer 2 (BN+ReLU fused into gemm2 load; transform then aggregate)
    k_gemm2<<<cdiv(n, 32), 384>>>(W2, n);
    k_agg12<<<cdiv(n * 3, B), B>>>(out, b2, n);
}

// round 17
// speedup vs baseline: 1.1517x; 1.1081x over previous
#include <cuda_runtime.h>
#include <cuda_fp16.h>
#include <cstdint>

#define HIDF 128
#define INF 16
#define OUTF 12
#define EPSF 1e-5f
#define NMAX 100000
#define EMAX 1600000
#define NSB  3200

// ---------------- device scratch (static, no allocation) ----------------
__device__ int   g_bad;
__device__ int   g_esrc[EMAX];
__device__ int   g_edst[EMAX];
__device__ int   g_cnt[NMAX];
__device__ int   g_rowptr[NMAX + 1];
__device__ int   g_bsumx[128];
__device__ int   g_src[EMAX];
__device__ float g_nrm[EMAX];
__device__ float g_degf[NMAX];
__device__ float g_dinv[NMAX];
__device__ __align__(16) float  g_aggX[NMAX * INF];
__device__ __align__(16) float  g_bufA[NMAX * HIDF];
__device__ __align__(16) float  g_bufB[NMAX * HIDF];
__device__ __align__(16) __half g_bufH[NMAX * HIDF];
__device__ __align__(16) float  g_psum[NSB * HIDF];
__device__ __align__(16) float  g_psq [NSB * HIDF];
__device__ __align__(16) float  g_bn[2 * HIDF];   // [scale, shift]

static inline int cdiv(int a, int b) { return (a + b - 1) / b; }

__device__ __forceinline__ float f2tf32f(float v) {
    uint32_t r;
    asm("cvt.rna.tf32.f32 %0, %1;" : "=r"(r) : "f"(v));
    return __uint_as_float(r);
}

#define MMA_TF32(d, a, b)                                                     \
    asm volatile(                                                             \
        "mma.sync.aligned.m16n8k8.row.col.f32.tf32.tf32.f32 "                 \
        "{%0,%1,%2,%3}, {%4,%5,%6,%7}, {%8,%9}, {%0,%1,%2,%3};"               \
        : "+f"(d[0]), "+f"(d[1]), "+f"(d[2]), "+f"(d[3])                      \
        : "r"(a[0]), "r"(a[1]), "r"(a[2]), "r"(a[3]), "r"(b[0]), "r"(b[1]))

// ---------------- zero + fused dtype detect (block 0) ----------------
__global__ void k_zero(const void* ei, int E, int n) {
    int i = blockIdx.x * blockDim.x + threadIdx.x;
    if (i < n) { g_cnt[i] = 0; g_degf[i] = 0.0f; }
    if (blockIdx.x == 0) {
        __shared__ int sbad;
        if (threadIdx.x == 0) sbad = 0;
        __syncthreads();
        int t = threadIdx.x;                 // 256 threads sample 1024 values
        int stride = (E > 1024) ? (E / 1024) : 1;
        int bad = 0;
        for (int j = 0; j < 4; j++) {
            long long idx = (long long)(t * 4 + j) * stride;
            if (idx < E) {
                long long v = ((const long long*)ei)[idx];
                if (v < 0 || v >= (long long)n) bad = 1;
            }
        }
        if (bad) sbad = 1;
        __syncthreads();
        if (t == 0) g_bad = sbad;            // sole writer, no init race
    }
}

// ---------------- repack + count + weighted degree (one edge pass) --------
__global__ void k_repack(const void* ei, const float* w, int E) {
    int e = blockIdx.x * blockDim.x + threadIdx.x;
    if (e < E) {
        int s, d;
        if (g_bad) {   // int32 layout
            const int* p = (const int*)ei;
            s = p[e]; d = p[E + e];
        } else {       // genuine int64 layout
            const long long* p = (const long long*)ei;
            s = (int)p[e]; d = (int)p[E + e];
        }
        g_esrc[e] = s;
        g_edst[e] = d;
        atomicAdd(&g_cnt[d], 1);
        atomicAdd(&g_degf[d], w[e]);
    }
}

// ---------------- CSR scan (+ fused dinv) ----------------
__global__ void k_scan_block(int n) {
    __shared__ int sh[256];
    int tid = threadIdx.x;
    int i0 = blockIdx.x * 1024 + tid * 4;
    int v0 = (i0 + 0 < n) ? g_cnt[i0 + 0] : 0;
    int v1 = (i0 + 1 < n) ? g_cnt[i0 + 1] : 0;
    int v2 = (i0 + 2 < n) ? g_cnt[i0 + 2] : 0;
    int v3 = (i0 + 3 < n) ? g_cnt[i0 + 3] : 0;
    int tot = v0 + v1 + v2 + v3;
    sh[tid] = tot;
    __syncthreads();
    for (int d = 1; d < 256; d <<= 1) {
        int t = (tid >= d) ? sh[tid - d] : 0;
        __syncthreads();
        sh[tid] += t;
        __syncthreads();
    }
    int run = sh[tid] - tot;
    run += v0; if (i0 + 0 < n) g_rowptr[i0 + 1] = run;
    run += v1; if (i0 + 1 < n) g_rowptr[i0 + 2] = run;
    run += v2; if (i0 + 2 < n) g_rowptr[i0 + 3] = run;
    run += v3; if (i0 + 3 < n) g_rowptr[i0 + 4] = run;
    if (tid == 255) g_bsumx[blockIdx.x] = sh[255];
#pragma unroll
    for (int j = 0; j < 4; j++) {
        int i = i0 + j;
        if (i < n) g_dinv[i] = rsqrtf(1.0f + g_degf[i]);   // +1 self-loop
    }
}

// ---------------- addoff with fused bsum reduction ----------------
__global__ void k_addoff(int n) {      // grid = nscan, 256 threads
    __shared__ int sh[256];
    int t = threadIdx.x;
    sh[t] = (t < blockIdx.x) ? g_bsumx[t] : 0;   // nscan <= 98 < 128
    __syncthreads();
    for (int d = 128; d > 0; d >>= 1) {
        if (t < d) sh[t] += sh[t + d];
        __syncthreads();
    }
    int base = sh[0];
    int i0 = blockIdx.x * 1024;
    for (int i = i0 + t; i < i0 + 1024; i += 256)
        if (i < n) g_rowptr[i + 1] += base;
    if (blockIdx.x == 0 && t == 0) g_rowptr[0] = 0;
}

// fillcsr: consumes g_cnt via atomicSub; fused normalization
__global__ void k_fillcsr(const float* w, int E) {
    int e = blockIdx.x * blockDim.x + threadIdx.x;
    if (e < E) {
        int src = g_esrc[e];
        int dst = g_edst[e];
        int pos = atomicSub(&g_cnt[dst], 1) - 1;   // 0..count-1 (reverse order)
        int idx = g_rowptr[dst] + pos;
        g_src[idx] = src;
        g_nrm[idx] = g_dinv[src] * w[e] * g_dinv[dst];
    }
}

// ---------------- layer0 aggregation: x (16 feats) -> aggX, float4 --------
__global__ void k_agg16(const float* x, int n) {
    int t = blockIdx.x * blockDim.x + threadIdx.x;   // 4 threads / node
    int node = t >> 2, q = t & 3;
    if (node < n) {
        float di = g_dinv[node];
        float ssc = di * di;
        float4 a = ((const float4*)x)[node * 4 + q];
        a.x *= ssc; a.y *= ssc; a.z *= ssc; a.w *= ssc;
        int s0 = g_rowptr[node], s1 = g_rowptr[node + 1];
        for (int s = s0; s < s1; s++) {
            float nv = g_nrm[s];
            float4 v = ((const float4*)x)[g_src[s] * 4 + q];
            a.x += v.x * nv; a.y += v.y * nv; a.z += v.z * nv; a.w += v.w * nv;
        }
        ((float4*)g_aggX)[node * 4 + q] = a;
    }
}

// ---------------- GEMM0 (+ fused BN stats, raw fp16 out): (N x 16)@(16 x 128)
__global__ void k_gemm0(const float* W, const float* bias, int n) {
    __shared__ float sW[INF * HIDF];
    __shared__ float sx[32 * INF];
    int tid = threadIdx.x;              // 128
    for (int idx = tid; idx < INF * HIDF; idx += 128) sW[idx] = W[idx];
    int base = blockIdx.x * 32;
    for (int idx = tid; idx < 32 * INF; idx += 128) {
        int r = idx >> 4, k = idx & 15;
        sx[idx] = (base + r < n) ? g_aggX[(base + r) * INF + k] : 0.0f;
    }
    __syncthreads();
    int col = tid;
    float wreg[INF];
#pragma unroll
    for (int k = 0; k < INF; k++) wreg[k] = sW[k * HIDF + col];
    float bb = bias[col];
    float ps = 0.0f, pq = 0.0f;
    for (int r = 0; r < 32; r++) {
        if (base + r < n) {
            float acc = bb;
#pragma unroll
            for (int k = 0; k < INF; k++) acc += sx[r * INF + k] * wreg[k];
            g_bufH[(base + r) * HIDF + col] = __float2half(acc);   // raw pre-BN fp16
            ps += acc; pq += acc * acc;                            // exact fp32 stats
        }
    }
    g_psum[blockIdx.x * HIDF + col] = ps;
    g_psq [blockIdx.x * HIDF + col] = pq;
}

// ---------------- BN finalize (parallel over columns) ----------------
__global__ void k_bnfin(const float* g, const float* be, int n, int nsb) {
    __shared__ float ssum[256], ssq[256];
    int c = blockIdx.x;                 // 0..127
    int t = threadIdx.x;                // 256
    float s = 0.0f, s2 = 0.0f;
    for (int b = t; b < nsb; b += 256) {
        s  += g_psum[b * HIDF + c];
        s2 += g_psq [b * HIDF + c];
    }
    ssum[t] = s; ssq[t] = s2;
    __syncthreads();
    for (int d = 128; d > 0; d >>= 1) {
        if (t < d) { ssum[t] += ssum[t + d]; ssq[t] += ssq[t + d]; }
        __syncthreads();
    }
    if (t == 0) {
        float inv_n = 1.0f / (float)n;
        float mean = ssum[0] * inv_n;
        float var = ssq[0] * inv_n - mean * mean;
        float sc = g[c] * rsqrtf(var + EPSF);
        g_bn[c] = sc;
        g_bn[HIDF + c] = be[c] - mean * sc;
    }
}

// ---------------- layer1 aggregation over raw fp16, BN+ReLU inline --------
__global__ void k_agg128(int n) {
    int t = blockIdx.x * blockDim.x + threadIdx.x;
    int node = t >> 5, lane = t & 31;
    if (node < n) {
        float4 sc4 = ((const float4*)g_bn)[lane];
        float4 sh4 = ((const float4*)g_bn)[32 + lane];
        float di = g_dinv[node];
        float ssc = di * di;
        float4 a;
        {
            uint2 raw = ((const uint2*)g_bufH)[node * 32 + lane];
            float2 f0 = __half22float2(*(__half2*)&raw.x);
            float2 f1 = __half22float2(*(__half2*)&raw.y);
            a.x = fmaxf(f0.x * sc4.x + sh4.x, 0.0f) * ssc;
            a.y = fmaxf(f0.y * sc4.y + sh4.y, 0.0f) * ssc;
            a.z = fmaxf(f1.x * sc4.z + sh4.z, 0.0f) * ssc;
            a.w = fmaxf(f1.y * sc4.w + sh4.w, 0.0f) * ssc;
        }
        int s0 = g_rowptr[node], s1 = g_rowptr[node + 1];
        for (int s = s0; s < s1; s++) {
            int src = g_src[s];               // broadcast within warp
            float nv = g_nrm[s];
            uint2 raw = ((const uint2*)g_bufH)[src * 32 + lane];
            float2 f0 = __half22float2(*(__half2*)&raw.x);
            float2 f1 = __half22float2(*(__half2*)&raw.y);
            a.x += fmaxf(f0.x * sc4.x + sh4.x, 0.0f) * nv;
            a.y += fmaxf(f0.y * sc4.y + sh4.y, 0.0f) * nv;
            a.z += fmaxf(f1.x * sc4.z + sh4.z, 0.0f) * nv;
            a.w += fmaxf(f1.y * sc4.w + sh4.w, 0.0f) * nv;
        }
        ((float4*)g_bufB)[node * 32 + lane] = a;
    }
}

// ---------------- GEMM1 (single-pass TF32 mma, 128x128 tile, + fused BN stats)
// 256 threads = 8 warps (2x4). Warp computes 64x32 via 4mt x 4nt m16n8k8 tiles.
__global__ void k_gemm1(const float* W, const float* bias, int n) {
    __shared__ float Ah[128][20];       // [row][k], stride 20: conflict-free frags
    __shared__ float Wh[16][132];       // [k][col]
    __shared__ float sSum[16][128];
    __shared__ float sSq [16][128];
    int tid = threadIdx.x;
    int warp = tid >> 5, lane = tid & 31;
    int wm = warp >> 2;          // 0..1
    int wn = warp & 3;           // 0..3
    int g  = lane >> 2;          // 0..7
    int tg = lane & 3;           // 0..3
    int rowBase = blockIdx.x * 128;

    float c[4][4][4];
#pragma unroll
    for (int mt = 0; mt < 4; mt++)
#pragma unroll
        for (int nt = 0; nt < 4; nt++)
#pragma unroll
            for (int j = 0; j < 4; j++) c[mt][nt][j] = 0.0f;

    for (int kc = 0; kc < HIDF; kc += 16) {
        // A tile: 128 rows x 16 k (hi-only tf32 round)
#pragma unroll
        for (int l = tid; l < 512; l += 256) {
            int r = l >> 2, q = l & 3;
            int row = rowBase + r;
            float4 v = make_float4(0.f, 0.f, 0.f, 0.f);
            if (row < n) v = *(const float4*)&g_bufB[row * HIDF + kc + q * 4];
            Ah[r][q * 4 + 0] = f2tf32f(v.x);
            Ah[r][q * 4 + 1] = f2tf32f(v.y);
            Ah[r][q * 4 + 2] = f2tf32f(v.z);
            Ah[r][q * 4 + 3] = f2tf32f(v.w);
        }
        // W chunk: 16 k x 128 cols (hi-only tf32 round)
#pragma unroll
        for (int l = tid; l < 512; l += 256) {
            int k = l >> 5, q = l & 31;
            float4 v = *(const float4*)&W[(kc + k) * HIDF + q * 4];
            Wh[k][q * 4 + 0] = f2tf32f(v.x);
            Wh[k][q * 4 + 1] = f2tf32f(v.y);
            Wh[k][q * 4 + 2] = f2tf32f(v.z);
            Wh[k][q * 4 + 3] = f2tf32f(v.w);
        }
        __syncthreads();
#pragma unroll
        for (int k8 = 0; k8 < 16; k8 += 8) {
            uint32_t ah[4][4];
#pragma unroll
            for (int mt = 0; mt < 4; mt++) {
                int r0 = wm * 64 + mt * 16 + g;
                ah[mt][0] = __float_as_uint(Ah[r0    ][k8 + tg]);
                ah[mt][1] = __float_as_uint(Ah[r0 + 8][k8 + tg]);
                ah[mt][2] = __float_as_uint(Ah[r0    ][k8 + tg + 4]);
                ah[mt][3] = __float_as_uint(Ah[r0 + 8][k8 + tg + 4]);
            }
#pragma unroll
            for (int nt = 0; nt < 4; nt++) {
                int col = wn * 32 + nt * 8 + g;
                uint32_t bh[2];
                bh[0] = __float_as_uint(Wh[k8 + tg    ][col]);
                bh[1] = __float_as_uint(Wh[k8 + tg + 4][col]);
#pragma unroll
                for (int mt = 0; mt < 4; mt++)
                    MMA_TF32(c[mt][nt], ah[mt], bh);
            }
        }
        __syncthreads();
    }
    // epilogue: + bias -> g_bufA (float2 stores), per-thread stats
    float ls[8] = {0,0,0,0,0,0,0,0};
    float lq[8] = {0,0,0,0,0,0,0,0};
#pragma unroll
    for (int nt = 0; nt < 4; nt++) {
        int col = wn * 32 + nt * 8 + 2 * tg;
        float b0 = bias[col], b1 = bias[col + 1];
#pragma unroll
        for (int mt = 0; mt < 4; mt++) {
            int row0 = rowBase + wm * 64 + mt * 16 + g;
            if (row0 < n) {
                float v0 = c[mt][nt][0] + b0;
                float v1 = c[mt][nt][1] + b1;
                *(float2*)&g_bufA[row0 * HIDF + col] = make_float2(v0, v1);
                ls[nt * 2] += v0; lq[nt * 2] += v0 * v0;
                ls[nt * 2 + 1] += v1; lq[nt * 2 + 1] += v1 * v1;
            }
            if (row0 + 8 < n) {
                float v2 = c[mt][nt][2] + b0;
                float v3 = c[mt][nt][3] + b1;
                *(float2*)&g_bufA[(row0 + 8) * HIDF + col] = make_float2(v2, v3);
                ls[nt * 2] += v2; lq[nt * 2] += v2 * v2;
                ls[nt * 2 + 1] += v3; lq[nt * 2 + 1] += v3 * v3;
            }
        }
    }
    // threads with same (wm,g) own disjoint column sets -> conflict-free rows
#pragma unroll
    for (int nt = 0; nt < 4; nt++) {
        int col = wn * 32 + nt * 8 + 2 * tg;
        sSum[wm * 8 + g][col]     = ls[nt * 2];
        sSum[wm * 8 + g][col + 1] = ls[nt * 2 + 1];
        sSq [wm * 8 + g][col]     = lq[nt * 2];
        sSq [wm * 8 + g][col + 1] = lq[nt * 2 + 1];
    }
    __syncthreads();
    if (tid < 128) {
        float s = 0.0f, q = 0.0f;
#pragma unroll
        for (int t = 0; t < 16; t++) { s += sSum[t][tid]; q += sSq[t][tid]; }
        g_psum[blockIdx.x * HIDF + tid] = s;
        g_psq [blockIdx.x * HIDF + tid] = q;
    }
}

// ---------------- GEMM2 (BN+ReLU fused on load): (N x 128) @ (128 x 12) -> bufB
__global__ void k_gemm2(const float* W, int n) {
    __shared__ float sW[HIDF * OUTF];    // 6KB
    __shared__ float sin[32 * HIDF];     // 16KB
    int tid = threadIdx.x;               // 384
    for (int idx = tid; idx < HIDF * OUTF; idx += 384) sW[idx] = W[idx];
    int base = blockIdx.x * 32;
    for (int idx = tid; idx < 32 * HIDF / 4; idx += 384) {   // 1024 float4
        int r = idx >> 5, q = idx & 31;
        float4 v = make_float4(0.f, 0.f, 0.f, 0.f);
        if (base + r < n) {
            float4 raw = *(const float4*)&g_bufA[(base + r) * HIDF + q * 4];
            float4 sc = ((const float4*)g_bn)[q];
            float4 sh = ((const float4*)g_bn)[32 + q];
            v.x = fmaxf(raw.x * sc.x + sh.x, 0.0f);
            v.y = fmaxf(raw.y * sc.y + sh.y, 0.0f);
            v.z = fmaxf(raw.z * sc.z + sh.z, 0.0f);
            v.w = fmaxf(raw.w * sc.w + sh.w, 0.0f);
        }
        *(float4*)&sin[r * HIDF + q * 4] = v;
    }
    __syncthreads();
    int c = tid % 12, r = tid / 12;      // r 0..31
    if (r < 32 && base + r < n) {
        float acc = 0.0f;
#pragma unroll 8
        for (int k = 0; k < HIDF; k++) acc += sin[r * HIDF + k] * sW[k * OUTF + c];
        g_bufB[(base + r) * OUTF + c] = acc;
    }
}

// ---------------- final aggregation (12 feats, float4): bufB -> out -------
__global__ void k_agg12(float* out, const float* b2, int n) {
    int t = blockIdx.x * blockDim.x + threadIdx.x;   // 3 float4-threads / node
    int node = t / 3, q = t - node * 3;
    if (node < n) {
        float di = g_dinv[node];
        float ssc = di * di;
        float4 a  = ((const float4*)g_bufB)[node * 3 + q];
        float4 bb = ((const float4*)b2)[q];
        a.x = a.x * ssc + bb.x; a.y = a.y * ssc + bb.y;
        a.z = a.z * ssc + bb.z; a.w = a.w * ssc + bb.w;
        int s0 = g_rowptr[node], s1 = g_rowptr[node + 1];
        for (int s = s0; s < s1; s++) {
            float nv = g_nrm[s];
            float4 v = ((const float4*)g_bufB)[g_src[s] * 3 + q];
            a.x += v.x * nv; a.y += v.y * nv; a.z += v.z * nv; a.w += v.w * nv;
        }
        ((float4*)out)[node * 3 + q] = a;
    }
}

// ---------------- launch ----------------
extern "C" void kernel_launch(void* const* d_in, const int* in_sizes, int n_in,
                              void* d_out, int out_size) {
    const float* x   = (const float*)d_in[0];
    const void*  ei  = d_in[1];
    const float* w   = (const float*)d_in[2];
    const float* W0  = (const float*)d_in[3];
    const float* b0  = (const float*)d_in[4];
    const float* W1  = (const float*)d_in[5];
    const float* b1  = (const float*)d_in[6];
    const float* W2  = (const float*)d_in[7];
    const float* b2  = (const float*)d_in[8];
    const float* g0  = (const float*)d_in[9];
    const float* be0 = (const float*)d_in[10];
    const float* g1  = (const float*)d_in[11];
    const float* be1 = (const float*)d_in[12];
    float* out = (float*)d_out;

    int n = in_sizes[0] / INF;
    int E = in_sizes[2];
    const int B = 256;
    int nscan = cdiv(n, 1024);
    int nsb0 = cdiv(n, 32);     // gemm0 stat blocks
    int nsb1 = cdiv(n, 128);    // gemm1 stat blocks

    // zero (+detect) + repack(+count+deg)
    k_zero<<<cdiv(n, B), B>>>(ei, E, n);
    k_repack<<<cdiv(E, B), B>>>(ei, w, E);

    // CSR build
    k_scan_block<<<nscan, 256>>>(n);
    k_addoff<<<nscan, 256>>>(n);
    k_fillcsr<<<cdiv(E, B), B>>>(w, E);

    // layer 0 (stats fused in gemm0 epilogue; raw fp16 output)
    k_agg16<<<cdiv(n * 4, B), B>>>(x, n);
    k_gemm0<<<nsb0, 128>>>(W0, b0, n);
    k_bnfin<<<HIDF, 256>>>(g0, be0, n, nsb0);

    // layer 1 (fp16 gather w/ inline BN; single-pass TF32 GEMM; stats fused)
    k_agg128<<<cdiv(n * 32, B), B>>>(n);
    k_gemm1<<<cdiv(n, 128), 256>>>(W1, b1, n);
    k_bnfin<<<HIDF, 256>>>(g1, be1, n, nsb1);

    // layer 2 (BN+ReLU fused into gemm2 load; transform then aggregate)
    k_gemm2<<<cdiv(n, 32), 384>>>(W2, n);
    k_agg12<<<cdiv(n * 3, B), B>>>(out, b2, n);
}